// round 10
// baseline (speedup 1.0000x reference)
#include <cuda_runtime.h>

#define NB 32
#define NCH 3
#define THREADS 128
#define B_PER_CHUNK 32
#define CHUNK_ELEMS (512*512)
#define CHUNK_F4   (CHUNK_ELEMS/4)         // 65536 float4 per (n,c) chunk
#define NCHUNKS    (16*3)                  // 48
#define NBLOCKS    (NCHUNKS * B_PER_CHUNK) // 1536 work blocks
#define STRIDE     (B_PER_CHUNK * THREADS) // 4096

// Global accumulators. Zero-initialized at module load; the waiter block
// resets them after reading, so every (graph-replayed) launch starts clean.
__device__ double g_sum_d[NCH * NB];
__device__ double g_cnt [NCH * NB];
__device__ unsigned int g_ticket;

__device__ __forceinline__ void accum(float2* h, float xc, float pc, float tc, int tid)
{
    int b = (int)(xc * 32.0f);        // inputs uniform [0,1)
    b = min(b, NB - 1);               // x slightly <1 can round x*32 up to 32.0
    float2* e = &h[b * THREADS + tid];
    float2 v = *e;                    // LDS.64, conflict-free (lane stride 8B)
    v.x += pc - tc;
    v.y += 1.0f;
    *e = v;                           // STS.64
}

__global__ __launch_bounds__(THREADS, 7)
void fused_kernel(const float4* __restrict__ pred,
                  const float4* __restrict__ targ,
                  const float4* __restrict__ x,
                  float* __restrict__ out)
{
    const int tid = threadIdx.x;

    // ---------------- dedicated waiter block (no histogram work) ----------
    if (blockIdx.x == NBLOCKS) {
        if (tid == 0) {
            unsigned int t;
            do {
                asm volatile("atom.acquire.gpu.global.add.u32 %0, [%1], %2;"
                             : "=r"(t) : "l"(&g_ticket), "r"(0u) : "memory");
                if (t < NBLOCKS) __nanosleep(100);
            } while (t < NBLOCKS);
        }
        __syncthreads();   // all waiter threads now ordered after the acquire

        float d = 0.0f;
        if (tid < NCH * NB) {
            float cnt = (float)g_cnt[tid];
            float sdv = (float)g_sum_d[tid];
            if (cnt > 0.0f) d = fabsf(sdv / cnt);
            g_sum_d[tid] = 0.0;       // reset for next launch (graph determinism)
            g_cnt [tid] = 0.0;
        }
        if (tid == 0) g_ticket = 0u;

        #pragma unroll
        for (int s = 16; s > 0; s >>= 1)
            d += __shfl_down_sync(0xffffffffu, d, s);

        __shared__ float wsum[4];
        if ((tid & 31) == 0) wsum[tid >> 5] = d;
        __syncthreads();
        if (tid == 0) out[0] = (wsum[0] + wsum[1] + wsum[2] + wsum[3]) / 96.0f;
        return;
    }

    // ---------------- work blocks: streaming histogram ---------------------
    __shared__ float2 h[NB * THREADS];

    #pragma unroll
    for (int b = 0; b < NB; b++)
        h[b * THREADS + tid] = make_float2(0.0f, 0.0f);
    __syncthreads();

    const int chunk = blockIdx.x / B_PER_CHUNK;   // (n*3 + c)
    const int sub   = blockIdx.x % B_PER_CHUNK;
    const int chan  = chunk % NCH;
    const size_t base = (size_t)chunk * CHUNK_F4;

    int i = sub * THREADS + tid;
    #pragma unroll 2
    for (int k = 0; k < CHUNK_F4 / (2 * STRIDE); k++, i += 2 * STRIDE) {
        float4 xa = __ldcs(&x   [base + i]);
        float4 pa = __ldcs(&pred[base + i]);
        float4 ta = __ldcs(&targ[base + i]);
        float4 xb = __ldcs(&x   [base + i + STRIDE]);
        float4 pb = __ldcs(&pred[base + i + STRIDE]);
        float4 tb = __ldcs(&targ[base + i + STRIDE]);

        accum(h, xa.x, pa.x, ta.x, tid);
        accum(h, xa.y, pa.y, ta.y, tid);
        accum(h, xa.z, pa.z, ta.z, tid);
        accum(h, xa.w, pa.w, ta.w, tid);

        accum(h, xb.x, pb.x, tb.x, tid);
        accum(h, xb.y, pb.y, tb.y, tid);
        accum(h, xb.z, pb.z, tb.z, tid);
        accum(h, xb.w, pb.w, tb.w, tid);
    }
    __syncthreads();

    // Block reduce: 128 threads = 32 bins x 4 quarters of 32 entries.
    const int bin = tid >> 2;
    const int j   = tid & 3;
    const int bi  = bin * THREADS + j * 32;

    float vd = 0.0f, vc = 0.0f;
    #pragma unroll
    for (int k = 0; k < 32; k++) {
        int kk = (k + tid) & 31;
        float2 e = h[bi + kk];
        vd += e.x;
        vc += e.y;
    }

    vd += __shfl_down_sync(0xffffffffu, vd, 1);
    vc += __shfl_down_sync(0xffffffffu, vc, 1);
    vd += __shfl_down_sync(0xffffffffu, vd, 2);
    vc += __shfl_down_sync(0xffffffffu, vc, 2);

    if (j == 0) {
        int g = chan * NB + bin;
        atomicAdd(&g_sum_d[g], (double)vd);   // L2 atomics
        atomicAdd(&g_cnt [g], (double)vc);
    }

    // Completion signal: non-returning release RED — block retires immediately,
    // no per-block round-trip on the shared counter (the R3/R9 pathology).
    __syncthreads();   // order all lanes' data atomics before the release
    if (tid == 0) {
        asm volatile("red.release.gpu.global.add.u32 [%0], %1;"
                     :: "l"(&g_ticket), "r"(1u) : "memory");
    }
}

extern "C" void kernel_launch(void* const* d_in, const int* in_sizes, int n_in,
                              void* d_out, int out_size)
{
    const float4* pred = (const float4*)d_in[0];
    const float4* targ = (const float4*)d_in[1];
    const float4* x    = (const float4*)d_in[2];
    float* out = (float*)d_out;

    fused_kernel<<<NBLOCKS + 1, THREADS>>>(pred, targ, x, out);
}

// round 11
// speedup vs baseline: 1.0065x; 1.0065x over previous
#include <cuda_runtime.h>

#define NB 32
#define NCH 3
#define THREADS 128
#define B_PER_CHUNK 32
#define CHUNK_ELEMS (512*512)
#define CHUNK_F4   (CHUNK_ELEMS/4)         // 65536 float4 per (n,c) chunk
#define NCHUNKS    (16*3)                  // 48
#define NBLOCKS    (NCHUNKS * B_PER_CHUNK) // 1536 work blocks
#define STRIDE     (B_PER_CHUNK * THREADS) // 4096
#define NSLOTS 32                          // contention spreading for fp64 atomics

// Slot-spread accumulators: per-address atomic chain depth = 1536/NSLOTS/3ch = 16.
// Zero-initialized at module load; waiter block resets after reading.
__device__ double g_sum_d[NSLOTS][NCH * NB];
__device__ double g_cnt [NSLOTS][NCH * NB];
__device__ unsigned int g_ticket;

__device__ __forceinline__ void accum(float2* h, float xc, float pc, float tc, int tid)
{
    int b = (int)(xc * 32.0f);        // inputs uniform [0,1)
    b = min(b, NB - 1);               // x slightly <1 can round x*32 up to 32.0
    float2* e = &h[b * THREADS + tid];
    float2 v = *e;                    // LDS.64, conflict-free (lane stride 8B)
    v.x += pc - tc;
    v.y += 1.0f;
    *e = v;                           // STS.64
}

__global__ __launch_bounds__(THREADS, 7)
void fused_kernel(const float4* __restrict__ pred,
                  const float4* __restrict__ targ,
                  const float4* __restrict__ x,
                  float* __restrict__ out)
{
    const int tid = threadIdx.x;

    // ---------------- dedicated waiter block (no histogram work) ----------
    if (blockIdx.x == NBLOCKS) {
        if (tid == 0) {
            unsigned int t;
            do {
                asm volatile("atom.acquire.gpu.global.add.u32 %0, [%1], %2;"
                             : "=r"(t) : "l"(&g_ticket), "r"(0u) : "memory");
                if (t < NBLOCKS) __nanosleep(100);
            } while (t < NBLOCKS);
        }
        __syncthreads();   // all waiter threads ordered after the acquire

        float d = 0.0f;
        if (tid < NCH * NB) {
            double sdv = 0.0, cnt = 0.0;
            #pragma unroll
            for (int s = 0; s < NSLOTS; s++) {
                sdv += g_sum_d[s][tid];
                cnt += g_cnt [s][tid];
                g_sum_d[s][tid] = 0.0;   // reset for next launch
                g_cnt [s][tid] = 0.0;
            }
            if (cnt > 0.0) d = (float)fabs(sdv / cnt);
        }
        if (tid == 0) g_ticket = 0u;

        #pragma unroll
        for (int s = 16; s > 0; s >>= 1)
            d += __shfl_down_sync(0xffffffffu, d, s);

        __shared__ float wsum[4];
        if ((tid & 31) == 0) wsum[tid >> 5] = d;
        __syncthreads();
        if (tid == 0) out[0] = (wsum[0] + wsum[1] + wsum[2] + wsum[3]) / 96.0f;
        return;
    }

    // ---------------- work blocks: streaming histogram ---------------------
    __shared__ float2 h[NB * THREADS];

    #pragma unroll
    for (int b = 0; b < NB; b++)
        h[b * THREADS + tid] = make_float2(0.0f, 0.0f);
    __syncthreads();

    const int chunk = blockIdx.x / B_PER_CHUNK;   // (n*3 + c)
    const int sub   = blockIdx.x % B_PER_CHUNK;
    const int chan  = chunk % NCH;
    const int slot  = blockIdx.x & (NSLOTS - 1);
    const size_t base = (size_t)chunk * CHUNK_F4;

    int i = sub * THREADS + tid;
    #pragma unroll 2
    for (int k = 0; k < CHUNK_F4 / (2 * STRIDE); k++, i += 2 * STRIDE) {
        float4 xa = __ldcs(&x   [base + i]);
        float4 pa = __ldcs(&pred[base + i]);
        float4 ta = __ldcs(&targ[base + i]);
        float4 xb = __ldcs(&x   [base + i + STRIDE]);
        float4 pb = __ldcs(&pred[base + i + STRIDE]);
        float4 tb = __ldcs(&targ[base + i + STRIDE]);

        accum(h, xa.x, pa.x, ta.x, tid);
        accum(h, xa.y, pa.y, ta.y, tid);
        accum(h, xa.z, pa.z, ta.z, tid);
        accum(h, xa.w, pa.w, ta.w, tid);

        accum(h, xb.x, pb.x, tb.x, tid);
        accum(h, xb.y, pb.y, tb.y, tid);
        accum(h, xb.z, pb.z, tb.z, tid);
        accum(h, xb.w, pb.w, tb.w, tid);
    }
    __syncthreads();

    // Block reduce: 128 threads = 32 bins x 4 quarters of 32 entries.
    const int bin = tid >> 2;
    const int j   = tid & 3;
    const int bi  = bin * THREADS + j * 32;

    float vd = 0.0f, vc = 0.0f;
    #pragma unroll
    for (int k = 0; k < 32; k++) {
        int kk = (k + tid) & 31;
        float2 e = h[bi + kk];
        vd += e.x;
        vc += e.y;
    }

    vd += __shfl_down_sync(0xffffffffu, vd, 1);
    vc += __shfl_down_sync(0xffffffffu, vc, 1);
    vd += __shfl_down_sync(0xffffffffu, vd, 2);
    vc += __shfl_down_sync(0xffffffffu, vc, 2);

    if (j == 0) {
        int g = chan * NB + bin;
        // slot-spread fp64 atomics: chain depth ~16 per address -> fast drain,
        // so the release-ordered ticket below clears quickly and the block
        // retires without the R3/R9/R10 retirement stall.
        atomicAdd(&g_sum_d[slot][g], (double)vd);
        atomicAdd(&g_cnt [slot][g], (double)vc);
    }

    __syncthreads();   // order all lanes' data atomics before the release
    if (tid == 0) {
        asm volatile("red.release.gpu.global.add.u32 [%0], %1;"
                     :: "l"(&g_ticket), "r"(1u) : "memory");
    }
}

extern "C" void kernel_launch(void* const* d_in, const int* in_sizes, int n_in,
                              void* d_out, int out_size)
{
    const float4* pred = (const float4*)d_in[0];
    const float4* targ = (const float4*)d_in[1];
    const float4* x    = (const float4*)d_in[2];
    float* out = (float*)d_out;

    fused_kernel<<<NBLOCKS + 1, THREADS>>>(pred, targ, x, out);
}